// round 2
// baseline (speedup 1.0000x reference)
#include <cuda_runtime.h>
#include <cuda_bf16.h>
#include <math.h>

// Problem constants (fixed by the dataset)
#define NN 50000
#define EE 800000
#define ET (NN + EE)       // edges + self loops
#define FD 256             // feature dim at every layer boundary (IN=H*HID=H*OUT=256)
#define NH 4
#define HF 64

// ---------------- scratch (no cudaMalloc allowed) ----------------
__device__ float    g_h   [NN * FD];      // per-layer projection h = in @ W
__device__ float    g_buf0[NN * FD];      // layer0 output
__device__ float    g_buf1[NN * FD];      // layer1 output
__device__ float    g_als [NN * NH];
__device__ float    g_ald [NN * NH];
__device__ unsigned g_emax[NN * NH];      // encoded float max
__device__ float    g_den [NN * NH];
__device__ float4   g_e   [ET];           // per-edge e / ee (4 heads)

// order-preserving encode for atomicMax on float
__device__ __forceinline__ unsigned encf(float f) {
    unsigned u = __float_as_uint(f);
    return (u & 0x80000000u) ? ~u : (u | 0x80000000u);
}
__device__ __forceinline__ float decf(unsigned u) {
    return (u & 0x80000000u) ? __uint_as_float(u & 0x7fffffffu) : __uint_as_float(~u);
}
#define ENC_NEG_INF 0x007FFFFFu   // encf(-inf)

__device__ __forceinline__ void atomicAddF4(float* p, float4 v) {
    asm volatile("red.global.add.v4.f32 [%0], {%1,%2,%3,%4};"
                 :: "l"(p), "f"(v.x), "f"(v.y), "f"(v.z), "f"(v.w) : "memory");
}

// ---------------- GEMM: C[N,256] = A[N,256] * B[256,256] ----------------
// BM=128, BN=64, BK=16, 256 threads, 8x4 per-thread tile.
__global__ __launch_bounds__(256) void gemm_k(
    const float* __restrict__ A, const float* __restrict__ B,
    float* __restrict__ C, int N)
{
    __shared__ float As[16][128];   // transposed: As[k][m]
    __shared__ float Bs[16][64];
    int tid = threadIdx.x;
    int bm = blockIdx.x * 128, bn = blockIdx.y * 64;
    int tr = tid >> 4, tc = tid & 15;    // 16x16 thread grid

    float acc[8][4] = {};
    for (int k0 = 0; k0 < FD; k0 += 16) {
        // load A tile 128x16 (2 float4/thread)
        #pragma unroll
        for (int i = 0; i < 2; i++) {
            int id = tid + i * 256;
            int r = id >> 2, c4 = (id & 3) * 4;
            int gr = bm + r;
            float4 v = make_float4(0.f, 0.f, 0.f, 0.f);
            if (gr < N) v = *(const float4*)(A + (size_t)gr * FD + k0 + c4);
            As[c4 + 0][r] = v.x; As[c4 + 1][r] = v.y;
            As[c4 + 2][r] = v.z; As[c4 + 3][r] = v.w;
        }
        // load B tile 16x64 (1 float4/thread)
        {
            int r = tid >> 4, c4 = (tid & 15) * 4;
            *(float4*)&Bs[r][c4] = *(const float4*)(B + (size_t)(k0 + r) * FD + bn + c4);
        }
        __syncthreads();
        #pragma unroll
        for (int k = 0; k < 16; k++) {
            float a[8], b[4];
            *(float4*)&a[0] = *(const float4*)&As[k][tr * 8];
            *(float4*)&a[4] = *(const float4*)&As[k][tr * 8 + 4];
            *(float4*)&b[0] = *(const float4*)&Bs[k][tc * 4];
            #pragma unroll
            for (int i = 0; i < 8; i++)
                #pragma unroll
                for (int j = 0; j < 4; j++)
                    acc[i][j] += a[i] * b[j];
        }
        __syncthreads();
    }
    #pragma unroll
    for (int i = 0; i < 8; i++) {
        int gr = bm + tr * 8 + i;
        if (gr < N) {
            float4 v = make_float4(acc[i][0], acc[i][1], acc[i][2], acc[i][3]);
            *(float4*)(C + (size_t)gr * FD + bn + tc * 4) = v;
        }
    }
}

// ---------------- per-layer init: out=bias, emax=-inf, denom=0 ----------------
__global__ void init_k(float* __restrict__ out, const float* __restrict__ b,
                       unsigned* __restrict__ emax, float* __restrict__ den, int N)
{
    int i = blockIdx.x * blockDim.x + threadIdx.x;
    if (i < N * FD) out[i] = b[i & (FD - 1)];
    if (i < N * NH) { emax[i] = ENC_NEG_INF; den[i] = 0.f; }
}

// ---------------- attention logits: warp per (node, head) ----------------
__global__ void att_k(const float* __restrict__ h,
                      const float* __restrict__ a_s, const float* __restrict__ a_d,
                      float* __restrict__ als, float* __restrict__ ald, int N)
{
    int w = (blockIdx.x * blockDim.x + threadIdx.x) >> 5;
    int lane = threadIdx.x & 31;
    if (w >= N * NH) return;
    int n = w >> 2, hd = w & 3;
    const float* hp = h + (size_t)n * FD + hd * HF;
    const float* sp = a_s + hd * HF;
    const float* dp = a_d + hd * HF;
    float s = hp[lane] * sp[lane] + hp[lane + 32] * sp[lane + 32];
    float d = hp[lane] * dp[lane] + hp[lane + 32] * dp[lane + 32];
    #pragma unroll
    for (int o = 16; o; o >>= 1) {
        s += __shfl_xor_sync(0xffffffffu, s, o);
        d += __shfl_xor_sync(0xffffffffu, d, o);
    }
    if (lane == 0) { als[n * NH + hd] = s; ald[n * NH + hd] = d; }
}

// ---------------- edge pass 1: e = leakyrelu(als[src]+ald[dst]); segment max ----------------
__device__ __forceinline__ float lrelu(float x) { return x > 0.f ? x : 0.2f * x; }

__global__ void edge_max_k(const int* __restrict__ ei,
                           const float* __restrict__ als, const float* __restrict__ ald,
                           float4* __restrict__ ebuf, unsigned* __restrict__ emax)
{
    int eid = blockIdx.x * blockDim.x + threadIdx.x;
    if (eid >= ET) return;
    int src, dst;
    if (eid < EE) { src = ei[eid]; dst = ei[EE + eid]; }
    else          { src = dst = eid - EE; }
    float4 s = *(const float4*)(als + (size_t)src * NH);
    float4 d = *(const float4*)(ald + (size_t)dst * NH);
    float4 e;
    e.x = lrelu(s.x + d.x); e.y = lrelu(s.y + d.y);
    e.z = lrelu(s.z + d.z); e.w = lrelu(s.w + d.w);
    ebuf[eid] = e;
    unsigned* em = emax + (size_t)dst * NH;
    atomicMax(em + 0, encf(e.x)); atomicMax(em + 1, encf(e.y));
    atomicMax(em + 2, encf(e.z)); atomicMax(em + 3, encf(e.w));
}

// ---------------- edge pass 2: ee = exp(e - emax[dst]); segment sum ----------------
__global__ void edge_exp_k(const int* __restrict__ ei,
                           float4* __restrict__ ebuf, const unsigned* __restrict__ emax,
                           float* __restrict__ den)
{
    int eid = blockIdx.x * blockDim.x + threadIdx.x;
    if (eid >= ET) return;
    int dst = (eid < EE) ? ei[EE + eid] : eid - EE;
    float4 e = ebuf[eid];
    const unsigned* em = emax + (size_t)dst * NH;
    float4 ee;
    ee.x = expf(e.x - decf(em[0]));
    ee.y = expf(e.y - decf(em[1]));
    ee.z = expf(e.z - decf(em[2]));
    ee.w = expf(e.w - decf(em[3]));
    ebuf[eid] = ee;
    atomicAddF4(den + (size_t)dst * NH, ee);
}

// ---------------- edge pass 3: out[dst] += alpha * h[src] (warp per edge) ----------------
__global__ void edge_scatter_k(const int* __restrict__ ei,
                               const float4* __restrict__ eebuf,
                               const float* __restrict__ den,
                               const float* __restrict__ h,
                               float* __restrict__ out)
{
    int w = (blockIdx.x * blockDim.x + threadIdx.x) >> 5;
    int lane = threadIdx.x & 31;
    if (w >= ET) return;
    int src, dst;
    if (w < EE) { src = ei[w]; dst = ei[EE + w]; }
    else        { src = dst = w - EE; }
    float4 ee = eebuf[w];                                   // broadcast
    float4 dn = *(const float4*)(den + (size_t)dst * NH);   // broadcast
    float a0 = ee.x / (dn.x + 1e-16f);
    float a1 = ee.y / (dn.y + 1e-16f);
    float a2 = ee.z / (dn.z + 1e-16f);
    float a3 = ee.w / (dn.w + 1e-16f);
    int hd = lane >> 3;                                     // 8 floats/lane -> one head
    float alpha = (hd == 0) ? a0 : (hd == 1) ? a1 : (hd == 2) ? a2 : a3;
    const float4* hs = (const float4*)(h + (size_t)src * FD);
    float4 v0 = hs[lane * 2], v1 = hs[lane * 2 + 1];
    v0.x *= alpha; v0.y *= alpha; v0.z *= alpha; v0.w *= alpha;
    v1.x *= alpha; v1.y *= alpha; v1.z *= alpha; v1.w *= alpha;
    float* op = out + (size_t)dst * FD + lane * 8;
    atomicAddF4(op, v0);
    atomicAddF4(op + 4, v1);
}

// ---------------- host side ----------------
static void run_layer(const float* in, float* out,
                      const float* W, const float* a_s, const float* a_d, const float* b,
                      const int* ei,
                      float* h, float* als, float* ald, unsigned* emax, float* den, float4* ebuf)
{
    int N = NN;
    dim3 ggrid((N + 127) / 128, FD / 64);
    gemm_k<<<ggrid, 256>>>(in, W, h, N);
    init_k<<<(N * FD + 255) / 256, 256>>>(out, b, emax, den, N);
    att_k<<<(N * NH * 32 + 255) / 256, 256>>>(h, a_s, a_d, als, ald, N);
    edge_max_k<<<(ET + 255) / 256, 256>>>(ei, als, ald, ebuf, emax);
    edge_exp_k<<<(ET + 255) / 256, 256>>>(ei, ebuf, emax, den);
    edge_scatter_k<<<((size_t)ET * 32 + 255) / 256, 256>>>(ei, ebuf, den, h, out);
}

extern "C" void kernel_launch(void* const* d_in, const int* in_sizes, int n_in,
                              void* d_out, int out_size)
{
    const float* x   = (const float*)d_in[0];
    const int*   ei  = (const int*)  d_in[1];
    const float* W0  = (const float*)d_in[2];
    const float* as0 = (const float*)d_in[3];
    const float* ad0 = (const float*)d_in[4];
    const float* b0  = (const float*)d_in[5];
    const float* W1  = (const float*)d_in[6];
    const float* as1 = (const float*)d_in[7];
    const float* ad1 = (const float*)d_in[8];
    const float* b1  = (const float*)d_in[9];
    const float* W2  = (const float*)d_in[10];
    const float* as2 = (const float*)d_in[11];
    const float* ad2 = (const float*)d_in[12];
    const float* b2  = (const float*)d_in[13];
    float* out = (float*)d_out;

    void *ph, *pb0, *pb1, *pals, *pald, *pemax, *pden, *pe;
    cudaGetSymbolAddress(&ph,   g_h);
    cudaGetSymbolAddress(&pb0,  g_buf0);
    cudaGetSymbolAddress(&pb1,  g_buf1);
    cudaGetSymbolAddress(&pals, g_als);
    cudaGetSymbolAddress(&pald, g_ald);
    cudaGetSymbolAddress(&pemax,g_emax);
    cudaGetSymbolAddress(&pden, g_den);
    cudaGetSymbolAddress(&pe,   g_e);

    float* h    = (float*)ph;
    float* buf0 = (float*)pb0;
    float* buf1 = (float*)pb1;
    float* als  = (float*)pals;
    float* ald  = (float*)pald;
    unsigned* emax = (unsigned*)pemax;
    float* den  = (float*)pden;
    float4* ebuf = (float4*)pe;

    run_layer(x,    buf0, W0, as0, ad0, b0, ei, h, als, ald, emax, den, ebuf);
    run_layer(buf0, buf1, W1, as1, ad1, b1, ei, h, als, ald, emax, den, ebuf);
    run_layer(buf1, out,  W2, as2, ad2, b2, ei, h, als, ald, emax, den, ebuf);
}

// round 3
// speedup vs baseline: 1.1433x; 1.1433x over previous
#include <cuda_runtime.h>
#include <cuda_bf16.h>
#include <math.h>

// Problem constants (fixed by the dataset)
#define NN 50000
#define EE 800000
#define ET (NN + EE)       // edges + self loops
#define FD 256             // feature dim at every layer boundary
#define NH 4
#define HF 64

// ---------------- scratch (no cudaMalloc allowed) ----------------
__device__ float g_h   [NN * FD];      // per-layer projection h = in @ W
__device__ float g_buf0[NN * FD];      // layer0 output
__device__ float g_buf1[NN * FD];      // layer1 output
__device__ float g_als [NN * NH];
__device__ float g_ald [NN * NH];
__device__ float g_den [NN * NH];

__device__ __forceinline__ void atomicAddF4(float* p, float4 v) {
    asm volatile("red.global.add.v4.f32 [%0], {%1,%2,%3,%4};"
                 :: "l"(p), "f"(v.x), "f"(v.y), "f"(v.z), "f"(v.w) : "memory");
}

__device__ __forceinline__ unsigned f2tf32(float x) {
    unsigned r;
    asm("cvt.rna.tf32.f32 %0, %1;" : "=r"(r) : "f"(x));
    return r;
}

// ---------------- TF32x3 GEMM: C[N,256] = A[N,256] * W[256,256] ----------------
// BM=128, BN=128, BK=16. 256 threads = 8 warps (2x4), warp tile 64x32.
// Split each operand into tf32 hi + lo; acc += Ah*Bh + Ah*Bl + Al*Bh (~fp32 accuracy).
#define SA 20    // A smem row stride (16 + 4 pad)
#define SB 132   // B smem row stride (128 + 4 pad)

#define MMA_TF32(c, a, b) \
    asm volatile("mma.sync.aligned.m16n8k8.row.col.f32.tf32.tf32.f32 " \
                 "{%0,%1,%2,%3}, {%4,%5,%6,%7}, {%8,%9}, {%0,%1,%2,%3};" \
                 : "+f"(c[0]), "+f"(c[1]), "+f"(c[2]), "+f"(c[3]) \
                 : "r"(a[0]), "r"(a[1]), "r"(a[2]), "r"(a[3]), "r"(b[0]), "r"(b[1]))

__global__ __launch_bounds__(256) void gemm_tf32_k(
    const float* __restrict__ A, const float* __restrict__ Bg,
    float* __restrict__ C, int N)
{
    __shared__ float Ah[128 * SA], Al[128 * SA];
    __shared__ float Bh[16 * SB],  Bl[16 * SB];
    int tid = threadIdx.x, lane = tid & 31, wid = tid >> 5;
    int bm = blockIdx.x * 128, bn = blockIdx.y * 128;
    int wm = (wid >> 2) * 64, wn = (wid & 3) * 32;
    int gr = lane >> 2, gc = lane & 3;

    float acc[4][4][4] = {};

    for (int k0 = 0; k0 < FD; k0 += 16) {
        // load + split A tile 128x16 (2 float4/thread)
        #pragma unroll
        for (int i = 0; i < 2; i++) {
            int s = tid + i * 256;
            int r = s >> 2, c4 = (s & 3) * 4;
            float4 v = make_float4(0.f, 0.f, 0.f, 0.f);
            if (bm + r < N) v = *(const float4*)(A + (size_t)(bm + r) * FD + k0 + c4);
            float4 hi, lo;
            hi.x = __uint_as_float(f2tf32(v.x)); lo.x = v.x - hi.x;
            hi.y = __uint_as_float(f2tf32(v.y)); lo.y = v.y - hi.y;
            hi.z = __uint_as_float(f2tf32(v.z)); lo.z = v.z - hi.z;
            hi.w = __uint_as_float(f2tf32(v.w)); lo.w = v.w - hi.w;
            *(float4*)&Ah[r * SA + c4] = hi;
            *(float4*)&Al[r * SA + c4] = lo;
        }
        // load + split B tile 16x128 (2 float4/thread)
        #pragma unroll
        for (int i = 0; i < 2; i++) {
            int s = tid + i * 256;
            int r = s >> 5, c4 = (s & 31) * 4;
            float4 v = *(const float4*)(Bg + (size_t)(k0 + r) * FD + bn + c4);
            float4 hi, lo;
            hi.x = __uint_as_float(f2tf32(v.x)); lo.x = v.x - hi.x;
            hi.y = __uint_as_float(f2tf32(v.y)); lo.y = v.y - hi.y;
            hi.z = __uint_as_float(f2tf32(v.z)); lo.z = v.z - hi.z;
            hi.w = __uint_as_float(f2tf32(v.w)); lo.w = v.w - hi.w;
            *(float4*)&Bh[r * SB + c4] = hi;
            *(float4*)&Bl[r * SB + c4] = lo;
        }
        __syncthreads();

        #pragma unroll
        for (int kk = 0; kk < 16; kk += 8) {
            unsigned ah[4][4], al[4][4], bh[4][2], bl[4][2];
            #pragma unroll
            for (int mt = 0; mt < 4; mt++) {
                int m = wm + mt * 16 + gr;
                const unsigned* p = (const unsigned*)Ah + m * SA + kk + gc;
                const unsigned* q = (const unsigned*)Al + m * SA + kk + gc;
                ah[mt][0] = p[0]; ah[mt][1] = p[8 * SA]; ah[mt][2] = p[4]; ah[mt][3] = p[8 * SA + 4];
                al[mt][0] = q[0]; al[mt][1] = q[8 * SA]; al[mt][2] = q[4]; al[mt][3] = q[8 * SA + 4];
            }
            #pragma unroll
            for (int nt = 0; nt < 4; nt++) {
                int n = wn + nt * 8 + gr;
                const unsigned* p = (const unsigned*)Bh + (kk + gc) * SB + n;
                const unsigned* q = (const unsigned*)Bl + (kk + gc) * SB + n;
                bh[nt][0] = p[0]; bh[nt][1] = p[4 * SB];
                bl[nt][0] = q[0]; bl[nt][1] = q[4 * SB];
            }
            #pragma unroll
            for (int mt = 0; mt < 4; mt++)
                #pragma unroll
                for (int nt = 0; nt < 4; nt++) {
                    MMA_TF32(acc[mt][nt], ah[mt], bh[nt]);
                    MMA_TF32(acc[mt][nt], ah[mt], bl[nt]);
                    MMA_TF32(acc[mt][nt], al[mt], bh[nt]);
                }
        }
        __syncthreads();
    }

    #pragma unroll
    for (int mt = 0; mt < 4; mt++)
        #pragma unroll
        for (int nt = 0; nt < 4; nt++) {
            int row = bm + wm + mt * 16 + gr;
            int col = bn + wn + nt * 8 + 2 * gc;
            if (row < N)
                *(float2*)(C + (size_t)row * FD + col) = make_float2(acc[mt][nt][0], acc[mt][nt][1]);
            if (row + 8 < N)
                *(float2*)(C + (size_t)(row + 8) * FD + col) = make_float2(acc[mt][nt][2], acc[mt][nt][3]);
        }
}

// ---------------- per-layer init: out=0, denom=0 ----------------
__global__ void init_k(float* __restrict__ out, float* __restrict__ den, int N)
{
    int i = blockIdx.x * blockDim.x + threadIdx.x;
    if (i < N * (FD / 4)) ((float4*)out)[i] = make_float4(0.f, 0.f, 0.f, 0.f);
    if (i < N * NH) den[i] = 0.f;
}

// ---------------- attention logits: warp per (node, head) ----------------
__global__ void att_k(const float* __restrict__ h,
                      const float* __restrict__ a_s, const float* __restrict__ a_d,
                      float* __restrict__ als, float* __restrict__ ald, int N)
{
    int w = (blockIdx.x * blockDim.x + threadIdx.x) >> 5;
    int lane = threadIdx.x & 31;
    if (w >= N * NH) return;
    int n = w >> 2, hd = w & 3;
    const float* hp = h + (size_t)n * FD + hd * HF;
    const float* sp = a_s + hd * HF;
    const float* dp = a_d + hd * HF;
    float s = hp[lane] * sp[lane] + hp[lane + 32] * sp[lane + 32];
    float d = hp[lane] * dp[lane] + hp[lane + 32] * dp[lane + 32];
    #pragma unroll
    for (int o = 16; o; o >>= 1) {
        s += __shfl_xor_sync(0xffffffffu, s, o);
        d += __shfl_xor_sync(0xffffffffu, d, o);
    }
    if (lane == 0) { als[n * NH + hd] = s; ald[n * NH + hd] = d; }
}

// ---------------- fused edge pass: ee=exp(lrelu(...)); den+=ee; out+=ee*h[src] ----------------
__device__ __forceinline__ float lrelu(float x) { return x > 0.f ? x : 0.2f * x; }

__global__ void edge_fused_k(const int* __restrict__ ei,
                             const float* __restrict__ als, const float* __restrict__ ald,
                             float* __restrict__ den,
                             const float* __restrict__ h,
                             float* __restrict__ out)
{
    int w = (blockIdx.x * blockDim.x + threadIdx.x) >> 5;
    int lane = threadIdx.x & 31;
    if (w >= ET) return;
    int src, dst;
    if (w < EE) { src = ei[w]; dst = ei[EE + w]; }
    else        { src = dst = w - EE; }
    float4 s = *(const float4*)(als + (size_t)src * NH);
    float4 d = *(const float4*)(ald + (size_t)dst * NH);
    float4 ee;
    ee.x = expf(lrelu(s.x + d.x));
    ee.y = expf(lrelu(s.y + d.y));
    ee.z = expf(lrelu(s.z + d.z));
    ee.w = expf(lrelu(s.w + d.w));
    if (lane == 0) atomicAddF4(den + (size_t)dst * NH, ee);
    int hd = lane >> 3;
    float alpha = (hd == 0) ? ee.x : (hd == 1) ? ee.y : (hd == 2) ? ee.z : ee.w;
    const float4* hs = (const float4*)(h + (size_t)src * FD);
    float4 v0 = hs[lane * 2], v1 = hs[lane * 2 + 1];
    v0.x *= alpha; v0.y *= alpha; v0.z *= alpha; v0.w *= alpha;
    v1.x *= alpha; v1.y *= alpha; v1.z *= alpha; v1.w *= alpha;
    float* op = out + (size_t)dst * FD + lane * 8;
    atomicAddF4(op, v0);
    atomicAddF4(op + 4, v1);
}

// ---------------- finalize: out = out/(den+eps) + bias ----------------
__global__ void fin_k(float* __restrict__ out, const float* __restrict__ den,
                      const float* __restrict__ b, int N)
{
    int i = blockIdx.x * blockDim.x + threadIdx.x;
    if (i >= N * (FD / 4)) return;
    int n = i >> 6, c4 = (i & 63) * 4;
    float inv = 1.f / (den[n * NH + (c4 >> 6)] + 1e-16f);
    float4 v = ((float4*)out)[i];
    float4 bb = *(const float4*)(b + c4);
    v.x = v.x * inv + bb.x; v.y = v.y * inv + bb.y;
    v.z = v.z * inv + bb.z; v.w = v.w * inv + bb.w;
    ((float4*)out)[i] = v;
}

// ---------------- host side ----------------
static void run_layer(const float* in, float* out,
                      const float* W, const float* a_s, const float* a_d, const float* b,
                      const int* ei,
                      float* h, float* als, float* ald, float* den)
{
    int N = NN;
    dim3 ggrid((N + 127) / 128, FD / 128);
    gemm_tf32_k<<<ggrid, 256>>>(in, W, h, N);
    init_k<<<(N * (FD / 4) + 255) / 256, 256>>>(out, den, N);
    att_k<<<(N * NH * 32 + 255) / 256, 256>>>(h, a_s, a_d, als, ald, N);
    edge_fused_k<<<((size_t)ET * 32 + 255) / 256, 256>>>(ei, als, ald, den, h, out);
    fin_k<<<(N * (FD / 4) + 255) / 256, 256>>>(out, den, b, N);
}

extern "C" void kernel_launch(void* const* d_in, const int* in_sizes, int n_in,
                              void* d_out, int out_size)
{
    const float* x   = (const float*)d_in[0];
    const int*   ei  = (const int*)  d_in[1];
    const float* W0  = (const float*)d_in[2];
    const float* as0 = (const float*)d_in[3];
    const float* ad0 = (const float*)d_in[4];
    const float* b0  = (const float*)d_in[5];
    const float* W1  = (const float*)d_in[6];
    const float* as1 = (const float*)d_in[7];
    const float* ad1 = (const float*)d_in[8];
    const float* b1  = (const float*)d_in[9];
    const float* W2  = (const float*)d_in[10];
    const float* as2 = (const float*)d_in[11];
    const float* ad2 = (const float*)d_in[12];
    const float* b2  = (const float*)d_in[13];
    float* out = (float*)d_out;

    void *ph, *pb0, *pb1, *pals, *pald, *pden;
    cudaGetSymbolAddress(&ph,   g_h);
    cudaGetSymbolAddress(&pb0,  g_buf0);
    cudaGetSymbolAddress(&pb1,  g_buf1);
    cudaGetSymbolAddress(&pals, g_als);
    cudaGetSymbolAddress(&pald, g_ald);
    cudaGetSymbolAddress(&pden, g_den);

    float* h    = (float*)ph;
    float* buf0 = (float*)pb0;
    float* buf1 = (float*)pb1;
    float* als  = (float*)pals;
    float* ald  = (float*)pald;
    float* den  = (float*)pden;

    run_layer(x,    buf0, W0, as0, ad0, b0, ei, h, als, ald, den);
    run_layer(buf0, buf1, W1, as1, ad1, b1, ei, h, als, ald, den);
    run_layer(buf1, out,  W2, as2, ad2, b2, ei, h, als, ald, den);
}

// round 4
// speedup vs baseline: 1.9846x; 1.7359x over previous
#include <cuda_runtime.h>
#include <cuda_bf16.h>
#include <math.h>

#define NN 50000
#define EE 800000
#define FD 256
#define NH 4
#define HF 64

// ---------------- scratch ----------------
__device__ float g_h   [NN * FD];
__device__ float g_buf0[NN * FD];
__device__ float g_buf1[NN * FD];
__device__ float g_als [NN * NH];
__device__ float g_ald [NN * NH];
__device__ int   g_deg [NN];
__device__ int   g_rowptr[NN + 1];
__device__ int   g_cursor[NN];
__device__ int   g_srcs[EE];

__device__ __forceinline__ unsigned f2tf32(float x) {
    unsigned r;
    asm("cvt.rna.tf32.f32 %0, %1;" : "=r"(r) : "f"(x));
    return r;
}

// ---------------- CSR build (once per call, reused by all 3 layers) ----------------
__global__ void deg_zero_k(int* __restrict__ deg) {
    int i = blockIdx.x * blockDim.x + threadIdx.x;
    if (i < NN) deg[i] = 0;
}
__global__ void deg_hist_k(const int* __restrict__ ei, int* __restrict__ deg) {
    int e = blockIdx.x * blockDim.x + threadIdx.x;
    if (e < EE) atomicAdd(deg + ei[EE + e], 1);
}
// single-block exclusive scan over 50000 degrees
__global__ __launch_bounds__(1024) void scan_k(const int* __restrict__ deg,
                                               int* __restrict__ rowptr,
                                               int* __restrict__ cursor) {
    __shared__ int ssum[1024];
    const int CH = 49;  // 1024*49 = 50176 >= NN
    int t = threadIdx.x;
    int base = t * CH;
    int s = 0;
    for (int i = 0; i < CH; i++) {
        int idx = base + i;
        if (idx < NN) s += deg[idx];
    }
    ssum[t] = s;
    __syncthreads();
    for (int o = 1; o < 1024; o <<= 1) {
        int u = (t >= o) ? ssum[t - o] : 0;
        __syncthreads();
        ssum[t] += u;
        __syncthreads();
    }
    int run = ssum[t] - s;   // exclusive offset of this chunk
    for (int i = 0; i < CH; i++) {
        int idx = base + i;
        if (idx <= NN) {
            if (idx < NN) {
                rowptr[idx] = run;
                cursor[idx] = run;
                run += deg[idx];
            } else {
                rowptr[NN] = run;
            }
        }
    }
}
__global__ void fill_k(const int* __restrict__ ei, int* __restrict__ cursor,
                       int* __restrict__ srcs) {
    int e = blockIdx.x * blockDim.x + threadIdx.x;
    if (e >= EE) return;
    int dst = ei[EE + e];
    int pos = atomicAdd(cursor + dst, 1);
    srcs[pos] = ei[e];
}

// ---------------- TF32x3 GEMM: C[N,256] = A[N,256] * W[256,256] ----------------
#define SA 20
#define SB 132
#define MMA_TF32(c, a, b) \
    asm volatile("mma.sync.aligned.m16n8k8.row.col.f32.tf32.tf32.f32 " \
                 "{%0,%1,%2,%3}, {%4,%5,%6,%7}, {%8,%9}, {%0,%1,%2,%3};" \
                 : "+f"(c[0]), "+f"(c[1]), "+f"(c[2]), "+f"(c[3]) \
                 : "r"(a[0]), "r"(a[1]), "r"(a[2]), "r"(a[3]), "r"(b[0]), "r"(b[1]))

__global__ __launch_bounds__(256) void gemm_tf32_k(
    const float* __restrict__ A, const float* __restrict__ Bg,
    float* __restrict__ C, int N)
{
    __shared__ float Ah[128 * SA], Al[128 * SA];
    __shared__ float Bh[16 * SB],  Bl[16 * SB];
    int tid = threadIdx.x, lane = tid & 31, wid = tid >> 5;
    int bm = blockIdx.x * 128, bn = blockIdx.y * 128;
    int wm = (wid >> 2) * 64, wn = (wid & 3) * 32;
    int gr = lane >> 2, gc = lane & 3;

    float acc[4][4][4] = {};

    for (int k0 = 0; k0 < FD; k0 += 16) {
        #pragma unroll
        for (int i = 0; i < 2; i++) {
            int s = tid + i * 256;
            int r = s >> 2, c4 = (s & 3) * 4;
            float4 v = make_float4(0.f, 0.f, 0.f, 0.f);
            if (bm + r < N) v = *(const float4*)(A + (size_t)(bm + r) * FD + k0 + c4);
            float4 hi, lo;
            hi.x = __uint_as_float(f2tf32(v.x)); lo.x = v.x - hi.x;
            hi.y = __uint_as_float(f2tf32(v.y)); lo.y = v.y - hi.y;
            hi.z = __uint_as_float(f2tf32(v.z)); lo.z = v.z - hi.z;
            hi.w = __uint_as_float(f2tf32(v.w)); lo.w = v.w - hi.w;
            *(float4*)&Ah[r * SA + c4] = hi;
            *(float4*)&Al[r * SA + c4] = lo;
        }
        #pragma unroll
        for (int i = 0; i < 2; i++) {
            int s = tid + i * 256;
            int r = s >> 5, c4 = (s & 31) * 4;
            float4 v = *(const float4*)(Bg + (size_t)(k0 + r) * FD + bn + c4);
            float4 hi, lo;
            hi.x = __uint_as_float(f2tf32(v.x)); lo.x = v.x - hi.x;
            hi.y = __uint_as_float(f2tf32(v.y)); lo.y = v.y - hi.y;
            hi.z = __uint_as_float(f2tf32(v.z)); lo.z = v.z - hi.z;
            hi.w = __uint_as_float(f2tf32(v.w)); lo.w = v.w - hi.w;
            *(float4*)&Bh[r * SB + c4] = hi;
            *(float4*)&Bl[r * SB + c4] = lo;
        }
        __syncthreads();

        #pragma unroll
        for (int kk = 0; kk < 16; kk += 8) {
            unsigned ah[4][4], al[4][4], bh[4][2], bl[4][2];
            #pragma unroll
            for (int mt = 0; mt < 4; mt++) {
                int m = wm + mt * 16 + gr;
                const unsigned* p = (const unsigned*)Ah + m * SA + kk + gc;
                const unsigned* q = (const unsigned*)Al + m * SA + kk + gc;
                ah[mt][0] = p[0]; ah[mt][1] = p[8 * SA]; ah[mt][2] = p[4]; ah[mt][3] = p[8 * SA + 4];
                al[mt][0] = q[0]; al[mt][1] = q[8 * SA]; al[mt][2] = q[4]; al[mt][3] = q[8 * SA + 4];
            }
            #pragma unroll
            for (int nt = 0; nt < 4; nt++) {
                int n = wn + nt * 8 + gr;
                const unsigned* p = (const unsigned*)Bh + (kk + gc) * SB + n;
                const unsigned* q = (const unsigned*)Bl + (kk + gc) * SB + n;
                bh[nt][0] = p[0]; bh[nt][1] = p[4 * SB];
                bl[nt][0] = q[0]; bl[nt][1] = q[4 * SB];
            }
            #pragma unroll
            for (int mt = 0; mt < 4; mt++)
                #pragma unroll
                for (int nt = 0; nt < 4; nt++) {
                    MMA_TF32(acc[mt][nt], ah[mt], bh[nt]);
                    MMA_TF32(acc[mt][nt], ah[mt], bl[nt]);
                    MMA_TF32(acc[mt][nt], al[mt], bh[nt]);
                }
        }
        __syncthreads();
    }

    #pragma unroll
    for (int mt = 0; mt < 4; mt++)
        #pragma unroll
        for (int nt = 0; nt < 4; nt++) {
            int row = bm + wm + mt * 16 + gr;
            int col = bn + wn + nt * 8 + 2 * gc;
            if (row < N)
                *(float2*)(C + (size_t)row * FD + col) = make_float2(acc[mt][nt][0], acc[mt][nt][1]);
            if (row + 8 < N)
                *(float2*)(C + (size_t)(row + 8) * FD + col) = make_float2(acc[mt][nt][2], acc[mt][nt][3]);
        }
}

// ---------------- attention logits: warp per (node, head) ----------------
__global__ void att_k(const float* __restrict__ h,
                      const float* __restrict__ a_s, const float* __restrict__ a_d,
                      float* __restrict__ als, float* __restrict__ ald, int N)
{
    int w = (blockIdx.x * blockDim.x + threadIdx.x) >> 5;
    int lane = threadIdx.x & 31;
    if (w >= N * NH) return;
    int n = w >> 2, hd = w & 3;
    const float* hp = h + (size_t)n * FD + hd * HF;
    const float* sp = a_s + hd * HF;
    const float* dp = a_d + hd * HF;
    float s = hp[lane] * sp[lane] + hp[lane + 32] * sp[lane + 32];
    float d = hp[lane] * dp[lane] + hp[lane + 32] * dp[lane + 32];
    #pragma unroll
    for (int o = 16; o; o >>= 1) {
        s += __shfl_xor_sync(0xffffffffu, s, o);
        d += __shfl_xor_sync(0xffffffffu, d, o);
    }
    if (lane == 0) { als[n * NH + hd] = s; ald[n * NH + hd] = d; }
}

// ---------------- fused gather: warp per dst node, zero atomics ----------------
__device__ __forceinline__ float lrelu(float x) { return x > 0.f ? x : 0.2f * x; }

__global__ __launch_bounds__(256) void gather_k(
    const int* __restrict__ rowptr, const int* __restrict__ srcs,
    const float* __restrict__ als, const float* __restrict__ ald,
    const float* __restrict__ h, const float* __restrict__ bias,
    float* __restrict__ out)
{
    int w = (blockIdx.x * blockDim.x + threadIdx.x) >> 5;
    int lane = threadIdx.x & 31;
    if (w >= NN) return;
    int dst = w;
    // lane covers floats [lane*4, lane*4+4) (head hd0) and [128+lane*4, ...) (head hd1)
    int hd0 = lane >> 4;          // 0 or 1
    int hd1 = hd0 + 2;            // 2 or 3
    float ald0 = __ldg(ald + dst * NH + hd0);
    float ald1 = __ldg(ald + dst * NH + hd1);

    float4 acc0 = make_float4(0.f, 0.f, 0.f, 0.f);
    float4 acc1 = make_float4(0.f, 0.f, 0.f, 0.f);
    float den0 = 0.f, den1 = 0.f;

    // self loop
    {
        float ee0 = expf(lrelu(__ldg(als + dst * NH + hd0) + ald0));
        float ee1 = expf(lrelu(__ldg(als + dst * NH + hd1) + ald1));
        const float4* hs = (const float4*)(h + (size_t)dst * FD);
        float4 v0 = hs[lane], v1 = hs[lane + 32];
        acc0.x += ee0 * v0.x; acc0.y += ee0 * v0.y; acc0.z += ee0 * v0.z; acc0.w += ee0 * v0.w;
        acc1.x += ee1 * v1.x; acc1.y += ee1 * v1.y; acc1.z += ee1 * v1.z; acc1.w += ee1 * v1.w;
        den0 += ee0; den1 += ee1;
    }

    int beg = rowptr[dst], end = rowptr[dst + 1];
    for (int i = beg; i < end; i++) {
        int src = __ldg(srcs + i);
        float ee0 = expf(lrelu(__ldg(als + src * NH + hd0) + ald0));
        float ee1 = expf(lrelu(__ldg(als + src * NH + hd1) + ald1));
        const float4* hs = (const float4*)(h + (size_t)src * FD);
        float4 v0 = hs[lane], v1 = hs[lane + 32];
        acc0.x += ee0 * v0.x; acc0.y += ee0 * v0.y; acc0.z += ee0 * v0.z; acc0.w += ee0 * v0.w;
        acc1.x += ee1 * v1.x; acc1.y += ee1 * v1.y; acc1.z += ee1 * v1.z; acc1.w += ee1 * v1.w;
        den0 += ee0; den1 += ee1;
    }

    float inv0 = 1.f / (den0 + 1e-16f);
    float inv1 = 1.f / (den1 + 1e-16f);
    const float4* bp = (const float4*)bias;
    float4 b0 = bp[lane], b1 = bp[lane + 32];
    float4 o0, o1;
    o0.x = acc0.x * inv0 + b0.x; o0.y = acc0.y * inv0 + b0.y;
    o0.z = acc0.z * inv0 + b0.z; o0.w = acc0.w * inv0 + b0.w;
    o1.x = acc1.x * inv1 + b1.x; o1.y = acc1.y * inv1 + b1.y;
    o1.z = acc1.z * inv1 + b1.z; o1.w = acc1.w * inv1 + b1.w;
    float4* op = (float4*)(out + (size_t)dst * FD);
    op[lane] = o0;
    op[lane + 32] = o1;
}

// ---------------- host side ----------------
static void run_layer(const float* in, float* out,
                      const float* W, const float* a_s, const float* a_d, const float* b,
                      const int* rowptr, const int* srcs,
                      float* h, float* als, float* ald)
{
    int N = NN;
    dim3 ggrid((N + 127) / 128, FD / 128);
    gemm_tf32_k<<<ggrid, 256>>>(in, W, h, N);
    att_k<<<(N * NH * 32 + 255) / 256, 256>>>(h, a_s, a_d, als, ald, N);
    gather_k<<<(N * 32 + 255) / 256, 256>>>(rowptr, srcs, als, ald, h, b, out);
}

extern "C" void kernel_launch(void* const* d_in, const int* in_sizes, int n_in,
                              void* d_out, int out_size)
{
    const float* x   = (const float*)d_in[0];
    const int*   ei  = (const int*)  d_in[1];
    const float* W0  = (const float*)d_in[2];
    const float* as0 = (const float*)d_in[3];
    const float* ad0 = (const float*)d_in[4];
    const float* b0  = (const float*)d_in[5];
    const float* W1  = (const float*)d_in[6];
    const float* as1 = (const float*)d_in[7];
    const float* ad1 = (const float*)d_in[8];
    const float* b1  = (const float*)d_in[9];
    const float* W2  = (const float*)d_in[10];
    const float* as2 = (const float*)d_in[11];
    const float* ad2 = (const float*)d_in[12];
    const float* b2  = (const float*)d_in[13];
    float* out = (float*)d_out;

    void *ph, *pb0, *pb1, *pals, *pald, *pdeg, *prp, *pcur, *psrc;
    cudaGetSymbolAddress(&ph,   g_h);
    cudaGetSymbolAddress(&pb0,  g_buf0);
    cudaGetSymbolAddress(&pb1,  g_buf1);
    cudaGetSymbolAddress(&pals, g_als);
    cudaGetSymbolAddress(&pald, g_ald);
    cudaGetSymbolAddress(&pdeg, g_deg);
    cudaGetSymbolAddress(&prp,  g_rowptr);
    cudaGetSymbolAddress(&pcur, g_cursor);
    cudaGetSymbolAddress(&psrc, g_srcs);

    float* h    = (float*)ph;
    float* buf0 = (float*)pb0;
    float* buf1 = (float*)pb1;
    float* als  = (float*)pals;
    float* ald  = (float*)pald;
    int* deg    = (int*)pdeg;
    int* rowptr = (int*)prp;
    int* cursor = (int*)pcur;
    int* srcs   = (int*)psrc;

    // CSR build (dst-sorted), reused by all 3 layers
    deg_zero_k<<<(NN + 255) / 256, 256>>>(deg);
    deg_hist_k<<<(EE + 255) / 256, 256>>>(ei, deg);
    scan_k<<<1, 1024>>>(deg, rowptr, cursor);
    fill_k<<<(EE + 255) / 256, 256>>>(ei, cursor, srcs);

    run_layer(x,    buf0, W0, as0, ad0, b0, rowptr, srcs, h, als, ald);
    run_layer(buf0, buf1, W1, as1, ad1, b1, rowptr, srcs, h, als, ald);
    run_layer(buf1, out,  W2, as2, ad2, b2, rowptr, srcs, h, als, ald);
}

// round 5
// speedup vs baseline: 2.4671x; 1.2432x over previous
#include <cuda_runtime.h>
#include <cuda_bf16.h>
#include <math.h>

#define NN 50000
#define EE 800000
#define FD 256
#define NH 4
#define HF 64

// ---------------- scratch ----------------
__device__ float g_h   [NN * FD];
__device__ float g_buf0[NN * FD];
__device__ float g_buf1[NN * FD];
__device__ float g_als [NN * NH];
__device__ float g_ald [NN * NH];
__device__ int   g_deg [NN];
__device__ int   g_rowptr[NN + 1];
__device__ int   g_cursor[NN];
__device__ int   g_srcs[EE];

// ---------------- CSR build (once per call, reused by all 3 layers) ----------------
__global__ void deg_zero_k(int* __restrict__ deg) {
    int i = blockIdx.x * blockDim.x + threadIdx.x;
    if (i < NN) deg[i] = 0;
}
__global__ void deg_hist_k(const int* __restrict__ ei, int* __restrict__ deg) {
    int e = blockIdx.x * blockDim.x + threadIdx.x;
    if (e < EE) atomicAdd(deg + ei[EE + e], 1);
}
__global__ __launch_bounds__(1024) void scan_k(const int* __restrict__ deg,
                                               int* __restrict__ rowptr,
                                               int* __restrict__ cursor) {
    __shared__ int ssum[1024];
    const int CH = 49;
    int t = threadIdx.x;
    int base = t * CH;
    int s = 0;
    for (int i = 0; i < CH; i++) {
        int idx = base + i;
        if (idx < NN) s += deg[idx];
    }
    ssum[t] = s;
    __syncthreads();
    for (int o = 1; o < 1024; o <<= 1) {
        int u = (t >= o) ? ssum[t - o] : 0;
        __syncthreads();
        ssum[t] += u;
        __syncthreads();
    }
    int run = ssum[t] - s;
    for (int i = 0; i < CH; i++) {
        int idx = base + i;
        if (idx <= NN) {
            if (idx < NN) {
                rowptr[idx] = run;
                cursor[idx] = run;
                run += deg[idx];
            } else {
                rowptr[NN] = run;
            }
        }
    }
}
__global__ void fill_k(const int* __restrict__ ei, int* __restrict__ cursor,
                       int* __restrict__ srcs) {
    int e = blockIdx.x * blockDim.x + threadIdx.x;
    if (e >= EE) return;
    int dst = ei[EE + e];
    int pos = atomicAdd(cursor + dst, 1);
    srcs[pos] = ei[e];
}

// ---------------- BF16x3 GEMM: C[N,256] = A[N,256] * W[256,256] ----------------
// BM=128, BN=128, BK=32. 256 threads = 8 warps (2x4), warp tile 64x32.
// x = hi(bf16) + lo(bf16); C ~= Ah*Bh + Ah*Bl + Al*Bh (residual ~2^-18).
#define SA2 20    // A smem row stride in uint (16 bf16x2 + 4 pad)
#define SB2 136   // B smem row stride in uint (128 + 8 pad)

#define MMA_BF16(c, a, b) \
    asm volatile("mma.sync.aligned.m16n8k16.row.col.f32.bf16.bf16.f32 " \
                 "{%0,%1,%2,%3}, {%4,%5,%6,%7}, {%8,%9}, {%0,%1,%2,%3};" \
                 : "+f"(c[0]), "+f"(c[1]), "+f"(c[2]), "+f"(c[3]) \
                 : "r"(a[0]), "r"(a[1]), "r"(a[2]), "r"(a[3]), "r"(b[0]), "r"(b[1]))

__device__ __forceinline__ void split2(float x, float y, unsigned& hi, unsigned& lo) {
    // pack (x -> low 16, y -> high 16) for both hi and lo parts
    __nv_bfloat16 hx = __float2bfloat16(x);
    __nv_bfloat16 hy = __float2bfloat16(y);
    float rx = x - __bfloat162float(hx);
    float ry = y - __bfloat162float(hy);
    __nv_bfloat162 h2 = __halves2bfloat162(hx, hy);   // .x low, .y high
    __nv_bfloat162 l2 = __floats2bfloat162_rn(rx, ry);
    hi = *(unsigned*)&h2;
    lo = *(unsigned*)&l2;
}

__global__ __launch_bounds__(256) void gemm_bf16x3_k(
    const float* __restrict__ A, const float* __restrict__ Bg,
    float* __restrict__ C, int N)
{
    __shared__ unsigned Ah2[128 * SA2], Al2[128 * SA2];
    __shared__ unsigned Bh2[16 * SB2],  Bl2[16 * SB2];
    int tid = threadIdx.x, lane = tid & 31, wid = tid >> 5;
    int bm = blockIdx.x * 128, bn = blockIdx.y * 128;
    int wm = (wid >> 2) * 64, wn = (wid & 3) * 32;
    int gr = lane >> 2, gc = lane & 3;

    float acc[4][4][4] = {};

    for (int k0 = 0; k0 < FD; k0 += 32) {
        // A tile 128x32 floats: 1024 float4 slots, 4 per thread
        #pragma unroll
        for (int i = 0; i < 4; i++) {
            int s = tid + i * 256;
            int r = s >> 3, c4 = (s & 7) * 4;     // float col base within 32
            float4 v = make_float4(0.f, 0.f, 0.f, 0.f);
            if (bm + r < N) v = *(const float4*)(A + (size_t)(bm + r) * FD + k0 + c4);
            unsigned h0, l0, h1, l1;
            split2(v.x, v.y, h0, l0);
            split2(v.z, v.w, h1, l1);
            int k2 = c4 >> 1;                     // bf16x2 index
            Ah2[r * SA2 + k2]     = h0;  Al2[r * SA2 + k2]     = l0;
            Ah2[r * SA2 + k2 + 1] = h1;  Al2[r * SA2 + k2 + 1] = l1;
        }
        // B tile 32x128 floats: pack over k pairs. 512 slots (16 k2-rows x 32 f4-cols), 2/thread
        #pragma unroll
        for (int i = 0; i < 2; i++) {
            int s = tid + i * 256;
            int k2 = s >> 5, c = (s & 31) * 4;
            const float* r0 = Bg + (size_t)(k0 + 2 * k2) * FD + bn + c;
            const float* r1 = r0 + FD;
            float4 ve = *(const float4*)r0;        // k even
            float4 vo = *(const float4*)r1;        // k odd
            unsigned h, l;
            split2(ve.x, vo.x, h, l); Bh2[k2 * SB2 + c + 0] = h; Bl2[k2 * SB2 + c + 0] = l;
            split2(ve.y, vo.y, h, l); Bh2[k2 * SB2 + c + 1] = h; Bl2[k2 * SB2 + c + 1] = l;
            split2(ve.z, vo.z, h, l); Bh2[k2 * SB2 + c + 2] = h; Bl2[k2 * SB2 + c + 2] = l;
            split2(ve.w, vo.w, h, l); Bh2[k2 * SB2 + c + 3] = h; Bl2[k2 * SB2 + c + 3] = l;
        }
        __syncthreads();

        #pragma unroll
        for (int g = 0; g < 2; g++) {             // two k16 groups per BK=32
            unsigned ah[4][4], al[4][4], bh[4][2], bl[4][2];
            #pragma unroll
            for (int mt = 0; mt < 4; mt++) {
                int m = wm + mt * 16 + gr;
                const unsigned* p = Ah2 + m * SA2 + g * 8 + gc;
                const unsigned* q = Al2 + m * SA2 + g * 8 + gc;
                ah[mt][0] = p[0]; ah[mt][1] = p[8 * SA2]; ah[mt][2] = p[4]; ah[mt][3] = p[8 * SA2 + 4];
                al[mt][0] = q[0]; al[mt][1] = q[8 * SA2]; al[mt][2] = q[4]; al[mt][3] = q[8 * SA2 + 4];
            }
            #pragma unroll
            for (int nt = 0; nt < 4; nt++) {
                int n = wn + nt * 8 + gr;
                const unsigned* p = Bh2 + (g * 8 + gc) * SB2 + n;
                const unsigned* q = Bl2 + (g * 8 + gc) * SB2 + n;
                bh[nt][0] = p[0]; bh[nt][1] = p[4 * SB2];
                bl[nt][0] = q[0]; bl[nt][1] = q[4 * SB2];
            }
            #pragma unroll
            for (int mt = 0; mt < 4; mt++)
                #pragma unroll
                for (int nt = 0; nt < 4; nt++) {
                    MMA_BF16(acc[mt][nt], ah[mt], bh[nt]);
                    MMA_BF16(acc[mt][nt], ah[mt], bl[nt]);
                    MMA_BF16(acc[mt][nt], al[mt], bh[nt]);
                }
        }
        __syncthreads();
    }

    #pragma unroll
    for (int mt = 0; mt < 4; mt++)
        #pragma unroll
        for (int nt = 0; nt < 4; nt++) {
            int row = bm + wm + mt * 16 + gr;
            int col = bn + wn + nt * 8 + 2 * gc;
            if (row < N)
                *(float2*)(C + (size_t)row * FD + col) = make_float2(acc[mt][nt][0], acc[mt][nt][1]);
            if (row + 8 < N)
                *(float2*)(C + (size_t)(row + 8) * FD + col) = make_float2(acc[mt][nt][2], acc[mt][nt][3]);
        }
}

// ---------------- attention logits: warp per (node, head) ----------------
__global__ void att_k(const float* __restrict__ h,
                      const float* __restrict__ a_s, const float* __restrict__ a_d,
                      float* __restrict__ als, float* __restrict__ ald, int N)
{
    int w = (blockIdx.x * blockDim.x + threadIdx.x) >> 5;
    int lane = threadIdx.x & 31;
    if (w >= N * NH) return;
    int n = w >> 2, hd = w & 3;
    const float* hp = h + (size_t)n * FD + hd * HF;
    const float* sp = a_s + hd * HF;
    const float* dp = a_d + hd * HF;
    float s = hp[lane] * sp[lane] + hp[lane + 32] * sp[lane + 32];
    float d = hp[lane] * dp[lane] + hp[lane + 32] * dp[lane + 32];
    #pragma unroll
    for (int o = 16; o; o >>= 1) {
        s += __shfl_xor_sync(0xffffffffu, s, o);
        d += __shfl_xor_sync(0xffffffffu, d, o);
    }
    if (lane == 0) { als[n * NH + hd] = s; ald[n * NH + hd] = d; }
}

// ---------------- fused gather: 2 warps per dst node (half row each) ----------------
__device__ __forceinline__ float lrelu(float x) { return x > 0.f ? x : 0.2f * x; }

__global__ __launch_bounds__(256) void gather_k(
    const int* __restrict__ rowptr, const int* __restrict__ srcs,
    const float* __restrict__ als, const float* __restrict__ ald,
    const float* __restrict__ h, const float* __restrict__ bias,
    float* __restrict__ out)
{
    int w = (blockIdx.x * blockDim.x + threadIdx.x) >> 5;
    int lane = threadIdx.x & 31;
    if (w >= NN * 2) return;
    int dst = w >> 1, half = w & 1;
    int f4 = half * 32 + lane;                 // float4 index within 64-wide row
    int hd = half * 2 + (lane >> 4);           // head owning this float4
    float aldv = __ldg(ald + dst * NH + hd);
    const float4* hp = (const float4*)h;

    float4 acc = make_float4(0.f, 0.f, 0.f, 0.f);
    float den = 0.f;

    // self loop
    {
        float ee = __expf(lrelu(__ldg(als + dst * NH + hd) + aldv));
        float4 v = hp[(size_t)dst * 64 + f4];
        acc.x += ee * v.x; acc.y += ee * v.y; acc.z += ee * v.z; acc.w += ee * v.w;
        den += ee;
    }

    int beg = rowptr[dst], end = rowptr[dst + 1];
    int i = beg;
    for (; i + 2 <= end; i += 2) {
        int s0 = __ldg(srcs + i), s1 = __ldg(srcs + i + 1);
        float e0 = __expf(lrelu(__ldg(als + s0 * NH + hd) + aldv));
        float e1 = __expf(lrelu(__ldg(als + s1 * NH + hd) + aldv));
        float4 v0 = hp[(size_t)s0 * 64 + f4];
        float4 v1 = hp[(size_t)s1 * 64 + f4];
        acc.x += e0 * v0.x + e1 * v1.x;
        acc.y += e0 * v0.y + e1 * v1.y;
        acc.z += e0 * v0.z + e1 * v1.z;
        acc.w += e0 * v0.w + e1 * v1.w;
        den += e0 + e1;
    }
    if (i < end) {
        int s0 = __ldg(srcs + i);
        float e0 = __expf(lrelu(__ldg(als + s0 * NH + hd) + aldv));
        float4 v0 = hp[(size_t)s0 * 64 + f4];
        acc.x += e0 * v0.x; acc.y += e0 * v0.y; acc.z += e0 * v0.z; acc.w += e0 * v0.w;
        den += e0;
    }

    float inv = 1.f / (den + 1e-16f);
    float4 b = ((const float4*)bias)[f4];
    float4 o;
    o.x = acc.x * inv + b.x; o.y = acc.y * inv + b.y;
    o.z = acc.z * inv + b.z; o.w = acc.w * inv + b.w;
    ((float4*)(out))[(size_t)dst * 64 + f4] = o;
}

// ---------------- host side ----------------
static void run_layer(const float* in, float* out,
                      const float* W, const float* a_s, const float* a_d, const float* b,
                      const int* rowptr, const int* srcs,
                      float* h, float* als, float* ald)
{
    int N = NN;
    dim3 ggrid((N + 127) / 128, FD / 128);
    gemm_bf16x3_k<<<ggrid, 256>>>(in, W, h, N);
    att_k<<<(N * NH * 32 + 255) / 256, 256>>>(h, a_s, a_d, als, ald, N);
    gather_k<<<(N * 2 * 32 + 255) / 256, 256>>>(rowptr, srcs, als, ald, h, b, out);
}

extern "C" void kernel_launch(void* const* d_in, const int* in_sizes, int n_in,
                              void* d_out, int out_size)
{
    const float* x   = (const float*)d_in[0];
    const int*   ei  = (const int*)  d_in[1];
    const float* W0  = (const float*)d_in[2];
    const float* as0 = (const float*)d_in[3];
    const float* ad0 = (const float*)d_in[4];
    const float* b0  = (const float*)d_in[5];
    const float* W1  = (const float*)d_in[6];
    const float* as1 = (const float*)d_in[7];
    const float* ad1 = (const float*)d_in[8];
    const float* b1  = (const float*)d_in[9];
    const float* W2  = (const float*)d_in[10];
    const float* as2 = (const float*)d_in[11];
    const float* ad2 = (const float*)d_in[12];
    const float* b2  = (const float*)d_in[13];
    float* out = (float*)d_out;

    void *ph, *pb0, *pb1, *pals, *pald, *pdeg, *prp, *pcur, *psrc;
    cudaGetSymbolAddress(&ph,   g_h);
    cudaGetSymbolAddress(&pb0,  g_buf0);
    cudaGetSymbolAddress(&pb1,  g_buf1);
    cudaGetSymbolAddress(&pals, g_als);
    cudaGetSymbolAddress(&pald, g_ald);
    cudaGetSymbolAddress(&pdeg, g_deg);
    cudaGetSymbolAddress(&prp,  g_rowptr);
    cudaGetSymbolAddress(&pcur, g_cursor);
    cudaGetSymbolAddress(&psrc, g_srcs);

    float* h    = (float*)ph;
    float* buf0 = (float*)pb0;
    float* buf1 = (float*)pb1;
    float* als  = (float*)pals;
    float* ald  = (float*)pald;
    int* deg    = (int*)pdeg;
    int* rowptr = (int*)prp;
    int* cursor = (int*)pcur;
    int* srcs   = (int*)psrc;

    deg_zero_k<<<(NN + 255) / 256, 256>>>(deg);
    deg_hist_k<<<(EE + 255) / 256, 256>>>(ei, deg);
    scan_k<<<1, 1024>>>(deg, rowptr, cursor);
    fill_k<<<(EE + 255) / 256, 256>>>(ei, cursor, srcs);

    run_layer(x,    buf0, W0, as0, ad0, b0, rowptr, srcs, h, als, ald);
    run_layer(buf0, buf1, W1, as1, ad1, b1, rowptr, srcs, h, als, ald);
    run_layer(buf1, out,  W2, as2, ad2, b2, rowptr, srcs, h, als, ald);
}

// round 6
// speedup vs baseline: 2.5128x; 1.0185x over previous
#include <cuda_runtime.h>
#include <cuda_bf16.h>
#include <math.h>

#define NN 50000
#define EE 800000
#define FD 256
#define NH 4
#define HF 64
#define K2 (FD / 2)       // 128 packed bf16x2 per row

// ---------------- scratch ----------------
__device__ float    g_h  [NN * FD];          // per-layer projection (fp32)
__device__ unsigned g_ahi[NN * K2];          // layer input, bf16 hi packed (k,k+1)
__device__ unsigned g_alo[NN * K2];          // layer input, bf16 lo packed
__device__ unsigned g_whi[3 * K2 * FD];      // weights pre-packed [layer][k2][n]
__device__ unsigned g_wlo[3 * K2 * FD];
__device__ float    g_als[NN * NH];
__device__ float    g_ald[NN * NH];
__device__ int      g_deg[NN];
__device__ int      g_rowptr[NN + 1];
__device__ int      g_cursor[NN];
__device__ int      g_srcs[EE];

__device__ __forceinline__ void split2(float x, float y, unsigned& hi, unsigned& lo) {
    __nv_bfloat16 hx = __float2bfloat16(x);
    __nv_bfloat16 hy = __float2bfloat16(y);
    float rx = x - __bfloat162float(hx);
    float ry = y - __bfloat162float(hy);
    __nv_bfloat162 h2 = __halves2bfloat162(hx, hy);
    __nv_bfloat162 l2 = __floats2bfloat162_rn(rx, ry);
    hi = *(unsigned*)&h2;
    lo = *(unsigned*)&l2;
}

// ---------------- CSR build ----------------
__global__ void deg_zero_k(int* __restrict__ deg) {
    int i = blockIdx.x * blockDim.x + threadIdx.x;
    if (i < NN) deg[i] = 0;
}
__global__ void deg_hist_k(const int* __restrict__ ei, int* __restrict__ deg) {
    int e = blockIdx.x * blockDim.x + threadIdx.x;
    if (e < EE) atomicAdd(deg + ei[EE + e], 1);
}
__global__ __launch_bounds__(1024) void scan_k(const int* __restrict__ deg,
                                               int* __restrict__ rowptr,
                                               int* __restrict__ cursor) {
    __shared__ int ssum[1024];
    const int CH = 49;
    int t = threadIdx.x;
    int base = t * CH;
    int s = 0;
    for (int i = 0; i < CH; i++) {
        int idx = base + i;
        if (idx < NN) s += deg[idx];
    }
    ssum[t] = s;
    __syncthreads();
    for (int o = 1; o < 1024; o <<= 1) {
        int u = (t >= o) ? ssum[t - o] : 0;
        __syncthreads();
        ssum[t] += u;
        __syncthreads();
    }
    int run = ssum[t] - s;
    for (int i = 0; i < CH; i++) {
        int idx = base + i;
        if (idx <= NN) {
            if (idx < NN) {
                rowptr[idx] = run;
                cursor[idx] = run;
                run += deg[idx];
            } else {
                rowptr[NN] = run;
            }
        }
    }
}
__global__ void fill_k(const int* __restrict__ ei, int* __restrict__ cursor,
                       int* __restrict__ srcs) {
    int e = blockIdx.x * blockDim.x + threadIdx.x;
    if (e >= EE) return;
    int dst = ei[EE + e];
    int pos = atomicAdd(cursor + dst, 1);
    srcs[pos] = ei[e];
}

// ---------------- operand pre-split ----------------
// x (fp32 row-major) -> packed bf16 hi/lo
__global__ void split_x_k(const float* __restrict__ x,
                          unsigned* __restrict__ hi, unsigned* __restrict__ lo) {
    int idx = blockIdx.x * blockDim.x + threadIdx.x;   // one float4 = 2 packed uints
    if (idx >= NN * 64) return;
    float4 v = ((const float4*)x)[idx];
    unsigned h0, l0, h1, l1;
    split2(v.x, v.y, h0, l0);
    split2(v.z, v.w, h1, l1);
    ((uint2*)hi)[idx] = make_uint2(h0, h1);
    ((uint2*)lo)[idx] = make_uint2(l0, l1);
}
// W[l] (fp32 [256,256] row-major, k-major rows) -> packed [k2][n]
__global__ void split_w_k(const float* __restrict__ W0, const float* __restrict__ W1,
                          const float* __restrict__ W2,
                          unsigned* __restrict__ hi, unsigned* __restrict__ lo) {
    int idx = blockIdx.x * blockDim.x + threadIdx.x;
    if (idx >= 3 * K2 * FD) return;
    int l = idx / (K2 * FD);
    int rem = idx - l * (K2 * FD);
    int k2 = rem >> 8, n = rem & 255;
    const float* W = (l == 0) ? W0 : (l == 1) ? W1 : W2;
    float a = W[(2 * k2) * FD + n];
    float b = W[(2 * k2 + 1) * FD + n];
    unsigned h, lw;
    split2(a, b, h, lw);
    hi[idx] = h;
    lo[idx] = lw;
}

// ---------------- BF16x3 GEMM with pre-split operands ----------------
// BM=128, BN=128, BK=32 (16 k2). 256 threads = 8 warps (2x4), warp tile 64x32.
#define SA2 20    // A smem row stride in uints (16 + 4 pad)
#define SB2 136   // B smem row stride in uints (128 + 8 pad)

#define MMA_BF16(c, a, b) \
    asm volatile("mma.sync.aligned.m16n8k16.row.col.f32.bf16.bf16.f32 " \
                 "{%0,%1,%2,%3}, {%4,%5,%6,%7}, {%8,%9}, {%0,%1,%2,%3};" \
                 : "+f"(c[0]), "+f"(c[1]), "+f"(c[2]), "+f"(c[3]) \
                 : "r"(a[0]), "r"(a[1]), "r"(a[2]), "r"(a[3]), "r"(b[0]), "r"(b[1]))

__global__ __launch_bounds__(256) void gemm_pre_k(
    const unsigned* __restrict__ Ahi, const unsigned* __restrict__ Alo,
    const unsigned* __restrict__ Whi, const unsigned* __restrict__ Wlo,
    float* __restrict__ C, int N)
{
    __shared__ unsigned Ah2[128 * SA2], Al2[128 * SA2];
    __shared__ unsigned Bh2[16 * SB2],  Bl2[16 * SB2];
    int tid = threadIdx.x, lane = tid & 31, wid = tid >> 5;
    int bm = blockIdx.x * 128, bn = blockIdx.y * 128;
    int wm = (wid >> 2) * 64, wn = (wid & 3) * 32;
    int gr = lane >> 2, gc = lane & 3;

    float acc[4][4][4] = {};

    for (int kb = 0; kb < K2; kb += 16) {
        // A tile: 128 rows x 16 uints; 512 uint4 slots, 2/thread per array
        #pragma unroll
        for (int i = 0; i < 2; i++) {
            int s = tid + i * 256;
            int r = s >> 2, c4 = (s & 3) * 4;
            uint4 vh = make_uint4(0, 0, 0, 0), vl = make_uint4(0, 0, 0, 0);
            if (bm + r < N) {
                size_t gidx = (size_t)(bm + r) * K2 + kb + c4;
                vh = *(const uint4*)(Ahi + gidx);
                vl = *(const uint4*)(Alo + gidx);
            }
            *(uint4*)&Ah2[r * SA2 + c4] = vh;
            *(uint4*)&Al2[r * SA2 + c4] = vl;
        }
        // B tile: 16 k2-rows x 128 uints; 512 uint4 slots, 2/thread per array
        #pragma unroll
        for (int i = 0; i < 2; i++) {
            int s = tid + i * 256;
            int r = s >> 5, c4 = (s & 31) * 4;
            size_t gidx = (size_t)(kb + r) * FD + bn + c4;
            *(uint4*)&Bh2[r * SB2 + c4] = *(const uint4*)(Whi + gidx);
            *(uint4*)&Bl2[r * SB2 + c4] = *(const uint4*)(Wlo + gidx);
        }
        __syncthreads();

        #pragma unroll
        for (int g = 0; g < 2; g++) {
            unsigned ah[4][4], al[4][4], bh[4][2], bl[4][2];
            #pragma unroll
            for (int mt = 0; mt < 4; mt++) {
                int m = wm + mt * 16 + gr;
                const unsigned* p = Ah2 + m * SA2 + g * 8 + gc;
                const unsigned* q = Al2 + m * SA2 + g * 8 + gc;
                ah[mt][0] = p[0]; ah[mt][1] = p[8 * SA2]; ah[mt][2] = p[4]; ah[mt][3] = p[8 * SA2 + 4];
                al[mt][0] = q[0]; al[mt][1] = q[8 * SA2]; al[mt][2] = q[4]; al[mt][3] = q[8 * SA2 + 4];
            }
            #pragma unroll
            for (int nt = 0; nt < 4; nt++) {
                int n = wn + nt * 8 + gr;
                const unsigned* p = Bh2 + (g * 8 + gc) * SB2 + n;
                const unsigned* q = Bl2 + (g * 8 + gc) * SB2 + n;
                bh[nt][0] = p[0]; bh[nt][1] = p[4 * SB2];
                bl[nt][0] = q[0]; bl[nt][1] = q[4 * SB2];
            }
            #pragma unroll
            for (int mt = 0; mt < 4; mt++)
                #pragma unroll
                for (int nt = 0; nt < 4; nt++) {
                    MMA_BF16(acc[mt][nt], ah[mt], bh[nt]);
                    MMA_BF16(acc[mt][nt], ah[mt], bl[nt]);
                    MMA_BF16(acc[mt][nt], al[mt], bh[nt]);
                }
        }
        __syncthreads();
    }

    #pragma unroll
    for (int mt = 0; mt < 4; mt++)
        #pragma unroll
        for (int nt = 0; nt < 4; nt++) {
            int row = bm + wm + mt * 16 + gr;
            int col = bn + wn + nt * 8 + 2 * gc;
            if (row < N)
                *(float2*)(C + (size_t)row * FD + col) = make_float2(acc[mt][nt][0], acc[mt][nt][1]);
            if (row + 8 < N)
                *(float2*)(C + (size_t)(row + 8) * FD + col) = make_float2(acc[mt][nt][2], acc[mt][nt][3]);
        }
}

// ---------------- attention logits: warp per (node, head) ----------------
__global__ void att_k(const float* __restrict__ h,
                      const float* __restrict__ a_s, const float* __restrict__ a_d,
                      float* __restrict__ als, float* __restrict__ ald, int N)
{
    int w = (blockIdx.x * blockDim.x + threadIdx.x) >> 5;
    int lane = threadIdx.x & 31;
    if (w >= N * NH) return;
    int n = w >> 2, hd = w & 3;
    const float* hp = h + (size_t)n * FD + hd * HF;
    const float* sp = a_s + hd * HF;
    const float* dp = a_d + hd * HF;
    float s = hp[lane] * sp[lane] + hp[lane + 32] * sp[lane + 32];
    float d = hp[lane] * dp[lane] + hp[lane + 32] * dp[lane + 32];
    #pragma unroll
    for (int o = 16; o; o >>= 1) {
        s += __shfl_xor_sync(0xffffffffu, s, o);
        d += __shfl_xor_sync(0xffffffffu, d, o);
    }
    if (lane == 0) { als[n * NH + hd] = s; ald[n * NH + hd] = d; }
}

// ---------------- fused gather: 2 warps per dst node ----------------
__device__ __forceinline__ float lrelu(float x) { return x > 0.f ? x : 0.2f * x; }

__global__ __launch_bounds__(256) void gather_k(
    const int* __restrict__ rowptr, const int* __restrict__ srcs,
    const float* __restrict__ als, const float* __restrict__ ald,
    const float* __restrict__ h, const float* __restrict__ bias,
    float* __restrict__ out_f32,
    unsigned* __restrict__ out_hi, unsigned* __restrict__ out_lo,
    int final_layer)
{
    int w = (blockIdx.x * blockDim.x + threadIdx.x) >> 5;
    int lane = threadIdx.x & 31;
    if (w >= NN * 2) return;
    int dst = w >> 1, half = w & 1;
    int f4 = half * 32 + lane;
    int hd = half * 2 + (lane >> 4);
    float aldv = __ldg(ald + dst * NH + hd);
    const float4* hp = (const float4*)h;

    float4 acc = make_float4(0.f, 0.f, 0.f, 0.f);
    float den = 0.f;

    // self loop
    {
        float ee = __expf(lrelu(__ldg(als + dst * NH + hd) + aldv));
        float4 v = hp[(size_t)dst * 64 + f4];
        acc.x += ee * v.x; acc.y += ee * v.y; acc.z += ee * v.z; acc.w += ee * v.w;
        den += ee;
    }

    int beg = rowptr[dst], end = rowptr[dst + 1];
    int i = beg;
    for (; i + 2 <= end; i += 2) {
        int s0 = __ldg(srcs + i), s1 = __ldg(srcs + i + 1);
        float e0 = __expf(lrelu(__ldg(als + s0 * NH + hd) + aldv));
        float e1 = __expf(lrelu(__ldg(als + s1 * NH + hd) + aldv));
        float4 v0 = hp[(size_t)s0 * 64 + f4];
        float4 v1 = hp[(size_t)s1 * 64 + f4];
        acc.x += e0 * v0.x + e1 * v1.x;
        acc.y += e0 * v0.y + e1 * v1.y;
        acc.z += e0 * v0.z + e1 * v1.z;
        acc.w += e0 * v0.w + e1 * v1.w;
        den += e0 + e1;
    }
    if (i < end) {
        int s0 = __ldg(srcs + i);
        float e0 = __expf(lrelu(__ldg(als + s0 * NH + hd) + aldv));
        float4 v0 = hp[(size_t)s0 * 64 + f4];
        acc.x += e0 * v0.x; acc.y += e0 * v0.y; acc.z += e0 * v0.z; acc.w += e0 * v0.w;
        den += e0;
    }

    float inv = 1.f / (den + 1e-16f);
    float4 b = ((const float4*)bias)[f4];
    float4 o;
    o.x = acc.x * inv + b.x; o.y = acc.y * inv + b.y;
    o.z = acc.z * inv + b.z; o.w = acc.w * inv + b.w;
    if (final_layer) {
        ((float4*)out_f32)[(size_t)dst * 64 + f4] = o;
    } else {
        unsigned h0, l0, h1, l1;
        split2(o.x, o.y, h0, l0);
        split2(o.z, o.w, h1, l1);
        ((uint2*)out_hi)[(size_t)dst * 64 + f4] = make_uint2(h0, h1);
        ((uint2*)out_lo)[(size_t)dst * 64 + f4] = make_uint2(l0, l1);
    }
}

// ---------------- host side ----------------
static void run_layer(const unsigned* whi, const unsigned* wlo,
                      const float* a_s, const float* a_d, const float* b,
                      const int* rowptr, const int* srcs,
                      unsigned* ahi, unsigned* alo,
                      float* h, float* als, float* ald,
                      float* out_f32, int final_layer)
{
    int N = NN;
    dim3 ggrid((N + 127) / 128, FD / 128);
    gemm_pre_k<<<ggrid, 256>>>(ahi, alo, whi, wlo, h, N);
    att_k<<<(N * NH * 32 + 255) / 256, 256>>>(h, a_s, a_d, als, ald, N);
    gather_k<<<(N * 2 * 32 + 255) / 256, 256>>>(rowptr, srcs, als, ald, h, b,
                                                out_f32, ahi, alo, final_layer);
}

extern "C" void kernel_launch(void* const* d_in, const int* in_sizes, int n_in,
                              void* d_out, int out_size)
{
    const float* x   = (const float*)d_in[0];
    const int*   ei  = (const int*)  d_in[1];
    const float* W0  = (const float*)d_in[2];
    const float* as0 = (const float*)d_in[3];
    const float* ad0 = (const float*)d_in[4];
    const float* b0  = (const float*)d_in[5];
    const float* W1  = (const float*)d_in[6];
    const float* as1 = (const float*)d_in[7];
    const float* ad1 = (const float*)d_in[8];
    const float* b1  = (const float*)d_in[9];
    const float* W2  = (const float*)d_in[10];
    const float* as2 = (const float*)d_in[11];
    const float* ad2 = (const float*)d_in[12];
    const float* b2  = (const float*)d_in[13];
    float* out = (float*)d_out;

    void *ph, *pahi, *palo, *pwhi, *pwlo, *pals, *pald, *pdeg, *prp, *pcur, *psrc;
    cudaGetSymbolAddress(&ph,   g_h);
    cudaGetSymbolAddress(&pahi, g_ahi);
    cudaGetSymbolAddress(&palo, g_alo);
    cudaGetSymbolAddress(&pwhi, g_whi);
    cudaGetSymbolAddress(&pwlo, g_wlo);
    cudaGetSymbolAddress(&pals, g_als);
    cudaGetSymbolAddress(&pald, g_ald);
    cudaGetSymbolAddress(&pdeg, g_deg);
    cudaGetSymbolAddress(&prp,  g_rowptr);
    cudaGetSymbolAddress(&pcur, g_cursor);
    cudaGetSymbolAddress(&psrc, g_srcs);

    float* h      = (float*)ph;
    unsigned* ahi = (unsigned*)pahi;
    unsigned* alo = (unsigned*)palo;
    unsigned* whi = (unsigned*)pwhi;
    unsigned* wlo = (unsigned*)pwlo;
    float* als    = (float*)pals;
    float* ald    = (float*)pald;
    int* deg      = (int*)pdeg;
    int* rowptr   = (int*)prp;
    int* cursor   = (int*)pcur;
    int* srcs     = (int*)psrc;

    // CSR build
    deg_zero_k<<<(NN + 255) / 256, 256>>>(deg);
    deg_hist_k<<<(EE + 255) / 256, 256>>>(ei, deg);
    scan_k<<<1, 1024>>>(deg, rowptr, cursor);
    fill_k<<<(EE + 255) / 256, 256>>>(ei, cursor, srcs);

    // operand pre-split
    split_x_k<<<(NN * 64 + 255) / 256, 256>>>(x, ahi, alo);
    split_w_k<<<(3 * K2 * FD + 255) / 256, 256>>>(W0, W1, W2, whi, wlo);

    run_layer(whi,               wlo,               as0, ad0, b0, rowptr, srcs, ahi, alo, h, als, ald, out, 0);
    run_layer(whi + K2 * FD,     wlo + K2 * FD,     as1, ad1, b1, rowptr, srcs, ahi, alo, h, als, ald, out, 0);
    run_layer(whi + 2 * K2 * FD, wlo + 2 * K2 * FD, as2, ad2, b2, rowptr, srcs, ahi, alo, h, als, ald, out, 1);
}